// round 5
// baseline (speedup 1.0000x reference)
#include <cuda_runtime.h>
#include <cstdint>

#define B_ 512
#define T_ 256
#define I_ 32
#define H_ 128

// 64MB scratch for layer-1 hidden sequence, (T, B, H) layout; + final h of layer 2
__device__ float g_h0[(size_t)T_ * B_ * H_];
__device__ float g_last[B_ * H_];

__device__ __forceinline__ void st_peer_f32(uint32_t laddr, int peer, float v) {
    uint32_t ra;
    asm volatile("mapa.shared::cluster.u32 %0, %1, %2;" : "=r"(ra) : "r"(laddr), "r"(peer));
    asm volatile("st.shared::cluster.f32 [%0], %1;" :: "r"(ra), "f"(v) : "memory");
}

__device__ __forceinline__ void cluster_sync_() {
    asm volatile("barrier.cluster.arrive.aligned;" ::: "memory");
    asm volatile("barrier.cluster.wait.aligned;" ::: "memory");
}

__device__ __forceinline__ float sigmoid_(float x) { return 1.f / (1.f + __expf(-x)); }
__device__ __forceinline__ float tanh_(float x)    { return 2.f / (1.f + __expf(-2.f * x)) - 1.f; }

// One LSTM layer, fused recurrence.
// Cluster of 4 CTAs; cluster owns 16 batch elements; CTA rank r owns h-dims
// [r*32, r*32+32) i.e. gate rows {g*128 + r*32 + d} for g in 0..3.
// KIN: input feature size (32 for layer1 reading x, 128 for layer2 reading h0).
// IN_TB: input layout is (T, B, KIN) if true, (B, T, KIN) if false.
// WRITE_SEQ: write full h sequence to out_seq (T,B,H); else only final h to out_last.
template <int KIN, bool IN_TB, bool WRITE_SEQ>
__global__ void __cluster_dims__(4, 1, 1) __launch_bounds__(128, 1)
lstm_layer(const float* __restrict__ in,
           const float* __restrict__ w_ih, const float* __restrict__ w_hh,
           const float* __restrict__ b_ih, const float* __restrict__ b_hh,
           float* __restrict__ out_seq, float* __restrict__ out_last)
{
    constexpr int KTOT  = KIN + H_;   // concatenated [input ; h] contraction dim
    constexpr int KHALF = KTOT / 2;

    extern __shared__ float smem[];
    float* w_s    = smem;               // [KTOT][128]  weights, k-major
    float* v0     = w_s + KTOT * 128;   // [KTOT][16]   input+h vector, buffer 0
    float* v1     = v0 + KTOT * 16;     // [KTOT][16]   buffer 1
    float* g_s    = v1 + KTOT * 16;     // [16][128]    gate preactivations
    float* bias_s = g_s + 2048;         // [128]
    float* c_s    = bias_s + 128;       // [16][32]     cell state (my 32 dims)

    const int tid    = threadIdx.x;
    const int rank   = blockIdx.x & 3;
    const int b_base = (blockIdx.x >> 2) * 16;

    // ---- load weights into SMEM, k-major: w_s[k][col], col = gate*32 + d ----
    for (int idx = tid; idx < 128 * KIN; idx += 128) {
        int col = idx / KIN, k = idx % KIN;
        int grow = (col >> 5) * 128 + rank * 32 + (col & 31);
        w_s[k * 128 + col] = w_ih[grow * KIN + k];
    }
    for (int idx = tid; idx < 128 * H_; idx += 128) {
        int col = idx / H_, k = idx % H_;
        int grow = (col >> 5) * 128 + rank * 32 + (col & 31);
        w_s[(KIN + k) * 128 + col] = w_hh[grow * H_ + k];
    }
    {
        int grow = (tid >> 5) * 128 + rank * 32 + (tid & 31);
        bias_s[tid] = b_ih[grow] + b_hh[grow];
    }
    for (int idx = tid; idx < KTOT * 16; idx += 128) v0[idx] = 0.f;
    for (int idx = tid; idx < 512; idx += 128) c_s[idx] = 0.f;
    __syncthreads();
    cluster_sync_();   // peers may DSMEM-write our v1 starting at t=0

    // thread tiling: kg in {0,1} (K split), bg in 0..3 (4 batches), cg in 0..15 (8 cols)
    const int kg  = tid >> 6;
    const int rem = tid & 63;
    const int bg  = rem >> 4;
    const int cg  = rem & 15;
    const int c0  = cg * 8;
    const int bl0 = bg * 4;

    for (int t = 0; t < T_; ++t) {
        float* vcur = (t & 1) ? v1 : v0;
        float* vnxt = (t & 1) ? v0 : v1;

        // ---- stage step-t input into vcur[k<KIN][b] ----
        if (IN_TB) {
            const float* src = in + ((size_t)t * B_ + b_base) * KIN;  // contiguous 16*KIN
            constexpr int NCH = (16 * KIN) / (128 * 4);
            #pragma unroll
            for (int c = 0; c < NCH; ++c) {
                int e = (c * 128 + tid) * 4;
                float4 x4 = *(const float4*)(src + e);
                int b = e / KIN, k = e % KIN;
                vcur[(k + 0) * 16 + b] = x4.x;
                vcur[(k + 1) * 16 + b] = x4.y;
                vcur[(k + 2) * 16 + b] = x4.z;
                vcur[(k + 3) * 16 + b] = x4.w;
            }
        } else {
            int b = tid >> 3, i0 = (tid & 7) * 4;   // KIN == 32
            const float* src = in + ((size_t)(b_base + b) * T_ + t) * KIN + i0;
            float4 x4 = *(const float4*)src;
            vcur[(i0 + 0) * 16 + b] = x4.x;
            vcur[(i0 + 1) * 16 + b] = x4.y;
            vcur[(i0 + 2) * 16 + b] = x4.z;
            vcur[(i0 + 3) * 16 + b] = x4.w;
        }
        __syncthreads();

        // ---- GEMM: acc[bi][j] = sum_k v[k][b] * w[k][col] (each kg does half of K) ----
        float acc[4][8];
        #pragma unroll
        for (int bi = 0; bi < 4; ++bi)
            #pragma unroll
            for (int j = 0; j < 8; ++j)
                acc[bi][j] = (kg == 0) ? bias_s[c0 + j] : 0.f;

        const int kbeg = kg * KHALF;
        #pragma unroll 4
        for (int k = kbeg; k < kbeg + KHALF; ++k) {
            float4 v4 = *(const float4*)(vcur + k * 16 + bl0);
            float4 wa = *(const float4*)(w_s + k * 128 + c0);
            float4 wb = *(const float4*)(w_s + k * 128 + c0 + 4);
            float va[4] = {v4.x, v4.y, v4.z, v4.w};
            float wv[8] = {wa.x, wa.y, wa.z, wa.w, wb.x, wb.y, wb.z, wb.w};
            #pragma unroll
            for (int bi = 0; bi < 4; ++bi)
                #pragma unroll
                for (int j = 0; j < 8; ++j)
                    acc[bi][j] = fmaf(va[bi], wv[j], acc[bi][j]);
        }

        // ---- K-split reduction into g_s ----
        if (kg == 1) {
            #pragma unroll
            for (int bi = 0; bi < 4; ++bi)
                #pragma unroll
                for (int j = 0; j < 8; ++j)
                    g_s[(bl0 + bi) * 128 + c0 + j] = acc[bi][j];
        }
        __syncthreads();
        if (kg == 0) {
            #pragma unroll
            for (int bi = 0; bi < 4; ++bi)
                #pragma unroll
                for (int j = 0; j < 8; ++j)
                    g_s[(bl0 + bi) * 128 + c0 + j] += acc[bi][j];
        }
        __syncthreads();

        // ---- pointwise gates + DSMEM h broadcast; 4 (b,d) pairs per thread ----
        #pragma unroll
        for (int j = 0; j < 4; ++j) {
            int p = tid * 4 + j;
            int b = p >> 5, d = p & 31;
            float gi = g_s[b * 128 + d];
            float gf = g_s[b * 128 + 32 + d];
            float gg = g_s[b * 128 + 64 + d];
            float go = g_s[b * 128 + 96 + d];
            float is = sigmoid_(gi);
            float fs = sigmoid_(gf);
            float gt = tanh_(gg);
            float os = sigmoid_(go);
            float c  = fs * c_s[b * 32 + d] + is * gt;
            c_s[b * 32 + d] = c;
            float h = os * tanh_(c);

            int hk = KIN + rank * 32 + d;
            float* dst = vnxt + hk * 16 + b;
            *dst = h;
            uint32_t la = (uint32_t)__cvta_generic_to_shared(dst);
            #pragma unroll
            for (int pr = 0; pr < 4; ++pr)
                if (pr != rank) st_peer_f32(la, pr, h);

            if (WRITE_SEQ) {
                out_seq[((size_t)t * B_ + (b_base + b)) * H_ + rank * 32 + d] = h;
            } else if (t == T_ - 1) {
                out_last[(size_t)(b_base + b) * H_ + rank * 32 + d] = h;
            }
        }
        cluster_sync_();   // release own h-slice to peers; acquire theirs
    }
}

// FC head: out[b] = fc2_b + sum_j fc2_w[j] * relu(fc1_b[j] + h1_last[b] . fc1_w[j])
__global__ void __launch_bounds__(64) fc_head(
    const float* __restrict__ last_h,
    const float* __restrict__ fc1_w, const float* __restrict__ fc1_b,
    const float* __restrict__ fc2_w, const float* __restrict__ fc2_b,
    float* __restrict__ out)
{
    int b = blockIdx.x, j = threadIdx.x;
    const float* h = last_h + (size_t)b * H_;
    const float* w = fc1_w + (size_t)j * H_;
    float s = fc1_b[j];
    #pragma unroll 8
    for (int k = 0; k < H_; ++k) s = fmaf(h[k], w[k], s);
    float z = fmaxf(s, 0.f) * fc2_w[j];

    __shared__ float red[2];
    #pragma unroll
    for (int o = 16; o > 0; o >>= 1) z += __shfl_down_sync(0xffffffff, z, o);
    if ((j & 31) == 0) red[j >> 5] = z;
    __syncthreads();
    if (j == 0) out[b] = red[0] + red[1] + fc2_b[0];
}

extern "C" void kernel_launch(void* const* d_in, const int* in_sizes, int n_in,
                              void* d_out, int out_size)
{
    const float* x     = (const float*)d_in[0];
    const float* w_ih0 = (const float*)d_in[1];
    const float* w_hh0 = (const float*)d_in[2];
    const float* b_ih0 = (const float*)d_in[3];
    const float* b_hh0 = (const float*)d_in[4];
    const float* w_ih1 = (const float*)d_in[5];
    const float* w_hh1 = (const float*)d_in[6];
    const float* b_ih1 = (const float*)d_in[7];
    const float* b_hh1 = (const float*)d_in[8];
    const float* fc1_w = (const float*)d_in[9];
    const float* fc1_b = (const float*)d_in[10];
    const float* fc2_w = (const float*)d_in[11];
    const float* fc2_b = (const float*)d_in[12];
    float* out = (float*)d_out;

    float *h0_ptr, *last_ptr;
    cudaGetSymbolAddress((void**)&h0_ptr, g_h0);
    cudaGetSymbolAddress((void**)&last_ptr, g_last);

    constexpr int SMEM1 = (160 * 128 + 2 * 160 * 16 + 2048 + 128 + 512) * 4;  // 113,152 B
    constexpr int SMEM2 = (256 * 128 + 2 * 256 * 16 + 2048 + 128 + 512) * 4;  // 174,592 B

    cudaFuncSetAttribute(lstm_layer<32, false, true>,
                         cudaFuncAttributeMaxDynamicSharedMemorySize, SMEM1);
    cudaFuncSetAttribute(lstm_layer<128, true, false>,
                         cudaFuncAttributeMaxDynamicSharedMemorySize, SMEM2);

    // layer 1: reads x (B,T,32) on the fly, writes h0 (T,B,128)
    lstm_layer<32, false, true><<<128, 128, SMEM1>>>(
        x, w_ih0, w_hh0, b_ih0, b_hh0, h0_ptr, nullptr);
    // layer 2: reads h0 (T,B,128), keeps only final h
    lstm_layer<128, true, false><<<128, 128, SMEM2>>>(
        h0_ptr, w_ih1, w_hh1, b_ih1, b_hh1, nullptr, last_ptr);
    // FC head
    fc_head<<<B_, 64>>>(last_ptr, fc1_w, fc1_b, fc2_w, fc2_b, out);

    (void)in_sizes; (void)n_in; (void)out_size;
}

// round 7
// speedup vs baseline: 1.0304x; 1.0304x over previous
#include <cuda_runtime.h>
#include <cstdint>

#define B_ 512
#define T_ 256
#define H_ 128
typedef unsigned long long ull;

// scratch: layer-1 hidden sequence (T, B, H) + final h of layer 2
__device__ float g_h0[(size_t)T_ * B_ * H_];
__device__ float g_last[B_ * H_];

// packed fp32x2 FMA: d = a * b + d  (Blackwell fma.rn.f32x2; ptxas never auto-emits)
#define FMA2(d, a, b) asm("fma.rn.f32x2 %0, %1, %2, %0;" : "+l"(d) : "l"(a), "l"(b))

__device__ __forceinline__ ull pack_dup(float v) {
    ull r; unsigned u = __float_as_uint(v);
    asm("mov.b64 %0, {%1, %1};" : "=l"(r) : "r"(u));
    return r;
}

__device__ __forceinline__ void st_peer_u64(uint32_t laddr, int peer, ull v) {
    uint32_t ra;
    asm volatile("mapa.shared::cluster.u32 %0, %1, %2;" : "=r"(ra) : "r"(laddr), "r"(peer));
    asm volatile("st.shared::cluster.b64 [%0], %1;" :: "r"(ra), "l"(v) : "memory");
}

__device__ __forceinline__ void cluster_arrive_() {
    asm volatile("barrier.cluster.arrive.aligned;" ::: "memory");
}
__device__ __forceinline__ void cluster_wait_() {
    asm volatile("barrier.cluster.wait.aligned;" ::: "memory");
}

__device__ __forceinline__ float sigmoid_(float x) { return 1.f / (1.f + __expf(-x)); }
__device__ __forceinline__ float tanh_(float x)    { return 2.f / (1.f + __expf(-2.f * x)) - 1.f; }

// One LSTM layer, fused recurrence. Cluster of 4 CTAs, 16 batch per cluster;
// CTA rank r owns h-dims [r*32, r*32+32) (gate rows g*128 + r*32 + d).
// v buffers hold (v,v)-DUPLICATED f32 pairs: row k = 32 floats = 16 batches' pairs.
// K-split-2 across warp halves; 2-col-packed f32x2 accumulators.
template <int KIN, bool IN_TB, bool WRITE_SEQ>
__global__ void __cluster_dims__(4, 1, 1) __launch_bounds__(256, 1)
lstm_layer(const float* __restrict__ in,
           const float* __restrict__ w_ih, const float* __restrict__ w_hh,
           const float* __restrict__ b_ih, const float* __restrict__ b_hh,
           float* __restrict__ out_seq, float* __restrict__ out_last)
{
    constexpr int KTOT  = KIN + H_;
    constexpr int KHALF = KTOT / 2;
    constexpr int GPAD  = 130;          // padded row stride to break STS conflicts

    extern __shared__ float smem[];
    float* w_s    = smem;               // [KTOT][128]  weights k-major (cols contiguous)
    float* vd0    = w_s + KTOT * 128;   // [KTOT][32]   dup (v,v) pairs, buffer 0
    float* vd1    = vd0 + KTOT * 32;    // buffer 1
    float* g0     = vd1 + KTOT * 32;    // [16][GPAD]   kg0 partial gates (incl. bias)
    float* g1     = g0 + 16 * GPAD;     // [16][GPAD]   kg1 partial gates
    float* bias_s = g1 + 16 * GPAD;     // [128]
    float* c_s    = bias_s + 128;       // [16][32]

    const int tid    = threadIdx.x;
    const int rank   = blockIdx.x & 3;
    const int b_base = (blockIdx.x >> 2) * 16;

    // ---- weights into SMEM: w_s[k][col], col = gate*32 + d ----
    for (int idx = tid; idx < 128 * KIN; idx += 256) {
        int col = idx / KIN, k = idx % KIN;
        int grow = (col >> 5) * 128 + rank * 32 + (col & 31);
        w_s[k * 128 + col] = w_ih[grow * KIN + k];
    }
    for (int idx = tid; idx < 128 * H_; idx += 256) {
        int col = idx / H_, k = idx % H_;
        int grow = (col >> 5) * 128 + rank * 32 + (col & 31);
        w_s[(KIN + k) * 128 + col] = w_hh[grow * H_ + k];
    }
    if (tid < 128) {
        int grow = (tid >> 5) * 128 + rank * 32 + (tid & 31);
        bias_s[tid] = b_ih[grow] + b_hh[grow];
    }
    for (int idx = tid; idx < 512; idx += 256) c_s[idx] = 0.f;
    for (int idx = tid; idx < H_ * 32; idx += 256) vd0[KIN * 32 + idx] = 0.f;  // h(-1)=0

    // ---- stage t=0 input into vd0 (dup pairs) ----
    if (IN_TB) {  // in is (T, B, KIN=128)
        const float* src = in + (size_t)b_base * KIN + tid * 8;
        float4 a = *(const float4*)src;
        float4 b4 = *(const float4*)(src + 4);
        int b = tid >> 4, k0 = (tid & 15) * 8;
        float* d0 = vd0 + 2 * b;
        *(ull*)(d0 + (k0 + 0) * 32) = pack_dup(a.x);
        *(ull*)(d0 + (k0 + 1) * 32) = pack_dup(a.y);
        *(ull*)(d0 + (k0 + 2) * 32) = pack_dup(a.z);
        *(ull*)(d0 + (k0 + 3) * 32) = pack_dup(a.w);
        *(ull*)(d0 + (k0 + 4) * 32) = pack_dup(b4.x);
        *(ull*)(d0 + (k0 + 5) * 32) = pack_dup(b4.y);
        *(ull*)(d0 + (k0 + 6) * 32) = pack_dup(b4.z);
        *(ull*)(d0 + (k0 + 7) * 32) = pack_dup(b4.w);
    } else {      // in is (B, T, KIN=32)
        #pragma unroll
        for (int i = 0; i < 2; ++i) {
            int idx = tid + i * 256;
            int b = idx >> 5, k = idx & 31;
            float v = in[((size_t)(b_base + b) * T_ + 0) * KIN + k];
            *(ull*)(vd0 + k * 32 + 2 * b) = pack_dup(v);
        }
    }
    __syncthreads();
    cluster_arrive_(); cluster_wait_();

    // ---- thread mapping ----
    const int kg   = tid >> 7;          // K half (warp-granular: no cross-k conflicts)
    const int lane = tid & 31;
    const int warp = tid >> 5;
    const int bg   = lane & 3;          // batch group (4 batches)
    const int cglo = lane >> 2;         // low col-group bits (8)
    const int cghi = warp & 3;          // high col-group bits (4)
    const int c0   = (cghi * 8 + cglo) * 4;   // 4 consecutive cols
    const int b0   = bg * 4;
    const int kbeg = kg * KHALF;
    float* gout = kg ? g1 : g0;

    for (int t = 0; t < T_; ++t) {
        float* vcur = (t & 1) ? vd1 : vd0;
        float* vnxt = (t & 1) ? vd0 : vd1;

        // ---- prefetch next-step input into registers (hide gmem latency) ----
        float  pf0 = 0.f, pf1 = 0.f;
        float4 pfa, pfb;
        if (t + 1 < T_) {
            if (IN_TB) {
                const float* src = in + ((size_t)(t + 1) * B_ + b_base) * KIN + tid * 8;
                pfa = *(const float4*)src;
                pfb = *(const float4*)(src + 4);
            } else {
                int i0 = tid, i1 = tid + 256;
                pf0 = in[((size_t)(b_base + (i0 >> 5)) * T_ + (t + 1)) * KIN + (i0 & 31)];
                pf1 = in[((size_t)(b_base + (i1 >> 5)) * T_ + (t + 1)) * KIN + (i1 & 31)];
            }
        }

        // ---- GEMM: acc2[bi][cj] covers (batch b0+bi, cols c0+2cj .. c0+2cj+1) ----
        ull acc[4][2];
        {
            ulonglong2 binit = *(const ulonglong2*)(bias_s + c0);
            #pragma unroll
            for (int bi = 0; bi < 4; ++bi) {
                acc[bi][0] = kg ? 0ull : binit.x;
                acc[bi][1] = kg ? 0ull : binit.y;
            }
        }
        #pragma unroll 8
        for (int k = kbeg; k < kbeg + KHALF; ++k) {
            ulonglong2 va = *(const ulonglong2*)(vcur + k * 32 + b0 * 2);     // (v,v) b0,b0+1
            ulonglong2 vb = *(const ulonglong2*)(vcur + k * 32 + b0 * 2 + 4); // (v,v) b0+2,b0+3
            ulonglong2 w2 = *(const ulonglong2*)(w_s + k * 128 + c0);         // (w0,w1),(w2,w3)
            FMA2(acc[0][0], va.x, w2.x); FMA2(acc[0][1], va.x, w2.y);
            FMA2(acc[1][0], va.y, w2.x); FMA2(acc[1][1], va.y, w2.y);
            FMA2(acc[2][0], vb.x, w2.x); FMA2(acc[2][1], vb.x, w2.y);
            FMA2(acc[3][0], vb.y, w2.x); FMA2(acc[3][1], vb.y, w2.y);
        }

        // ---- store partials (both K-halves), one barrier ----
        #pragma unroll
        for (int bi = 0; bi < 4; ++bi) {
            *(ull*)(gout + (b0 + bi) * GPAD + c0)     = acc[bi][0];
            *(ull*)(gout + (b0 + bi) * GPAD + c0 + 2) = acc[bi][1];
        }
        __syncthreads();

        // ---- pointwise gates + DSMEM h broadcast (2 (b,d) pairs per thread) ----
        #pragma unroll
        for (int j = 0; j < 2; ++j) {
            int p = tid * 2 + j;
            int b = p >> 5, d = p & 31;
            const float* ga = g0 + b * GPAD + d;
            const float* gb = g1 + b * GPAD + d;
            float gi = ga[0]  + gb[0];
            float gf = ga[32] + gb[32];
            float gg = ga[64] + gb[64];
            float go = ga[96] + gb[96];
            float is = sigmoid_(gi);
            float fs = sigmoid_(gf);
            float gt = tanh_(gg);
            float os = sigmoid_(go);
            float c  = fs * c_s[b * 32 + d] + is * gt;
            c_s[b * 32 + d] = c;
            float h  = os * tanh_(c);

            int hk = KIN + rank * 32 + d;
            float* dst = vnxt + hk * 32 + 2 * b;
            ull hh = pack_dup(h);
            *(ull*)dst = hh;
            uint32_t la = (uint32_t)__cvta_generic_to_shared(dst);
            if (rank != 0) st_peer_u64(la, 0, hh);
            if (rank != 1) st_peer_u64(la, 1, hh);
            if (rank != 2) st_peer_u64(la, 2, hh);
            if (rank != 3) st_peer_u64(la, 3, hh);

            if (WRITE_SEQ) {
                out_seq[((size_t)t * B_ + (b_base + b)) * H_ + rank * 32 + d] = h;
            } else if (t == T_ - 1) {
                out_last[(size_t)(b_base + b) * H_ + rank * 32 + d] = h;
            }
        }

        // release my h-slice; overlap local-only staging with cluster latency
        cluster_arrive_();
        if (t + 1 < T_) {
            if (IN_TB) {
                int b = tid >> 4, k0 = (tid & 15) * 8;
                float* d0 = vnxt + 2 * b;
                *(ull*)(d0 + (k0 + 0) * 32) = pack_dup(pfa.x);
                *(ull*)(d0 + (k0 + 1) * 32) = pack_dup(pfa.y);
                *(ull*)(d0 + (k0 + 2) * 32) = pack_dup(pfa.z);
                *(ull*)(d0 + (k0 + 3) * 32) = pack_dup(pfa.w);
                *(ull*)(d0 + (k0 + 4) * 32) = pack_dup(pfb.x);
                *(ull*)(d0 + (k0 + 5) * 32) = pack_dup(pfb.y);
                *(ull*)(d0 + (k0 + 6) * 32) = pack_dup(pfb.z);
                *(ull*)(d0 + (k0 + 7) * 32) = pack_dup(pfb.w);
            } else {
                int i0 = tid, i1 = tid + 256;
                *(ull*)(vnxt + (i0 & 31) * 32 + 2 * (i0 >> 5)) = pack_dup(pf0);
                *(ull*)(vnxt + (i1 & 31) * 32 + 2 * (i1 >> 5)) = pack_dup(pf1);
            }
        }
        cluster_wait_();
    }
}

// FC head: out[b] = fc2_b + sum_j fc2_w[j] * relu(fc1_b[j] + h1_last[b] . fc1_w[j])
__global__ void __launch_bounds__(64) fc_head(
    const float* __restrict__ last_h,
    const float* __restrict__ fc1_w, const float* __restrict__ fc1_b,
    const float* __restrict__ fc2_w, const float* __restrict__ fc2_b,
    float* __restrict__ out)
{
    int b = blockIdx.x, j = threadIdx.x;
    const float* h = last_h + (size_t)b * H_;
    const float* w = fc1_w + (size_t)j * H_;
    float s = fc1_b[j];
    #pragma unroll 8
    for (int k = 0; k < H_; ++k) s = fmaf(h[k], w[k], s);
    float z = fmaxf(s, 0.f) * fc2_w[j];

    __shared__ float red[2];
    #pragma unroll
    for (int o = 16; o > 0; o >>= 1) z += __shfl_down_sync(0xffffffff, z, o);
    if ((j & 31) == 0) red[j >> 5] = z;
    __syncthreads();
    if (j == 0) out[b] = red[0] + red[1] + fc2_b[0];
}

extern "C" void kernel_launch(void* const* d_in, const int* in_sizes, int n_in,
                              void* d_out, int out_size)
{
    const float* x     = (const float*)d_in[0];
    const float* w_ih0 = (const float*)d_in[1];
    const float* w_hh0 = (const float*)d_in[2];
    const float* b_ih0 = (const float*)d_in[3];
    const float* b_hh0 = (const float*)d_in[4];
    const float* w_ih1 = (const float*)d_in[5];
    const float* w_hh1 = (const float*)d_in[6];
    const float* b_ih1 = (const float*)d_in[7];
    const float* b_hh1 = (const float*)d_in[8];
    const float* fc1_w = (const float*)d_in[9];
    const float* fc1_b = (const float*)d_in[10];
    const float* fc2_w = (const float*)d_in[11];
    const float* fc2_b = (const float*)d_in[12];
    float* out = (float*)d_out;

    float *h0_ptr, *last_ptr;
    cudaGetSymbolAddress((void**)&h0_ptr, g_h0);
    cudaGetSymbolAddress((void**)&last_ptr, g_last);

    // floats: w KTOT*128, vdup 2*KTOT*32, g 2*16*130, bias 128, c 512
    constexpr int SMEM1 = (160 * 128 + 2 * 160 * 32 + 2 * 16 * 130 + 128 + 512) * 4; // 142,080
    constexpr int SMEM2 = (256 * 128 + 2 * 256 * 32 + 2 * 16 * 130 + 128 + 512) * 4; // 215,808

    cudaFuncSetAttribute(lstm_layer<32, false, true>,
                         cudaFuncAttributeMaxDynamicSharedMemorySize, SMEM1);
    cudaFuncSetAttribute(lstm_layer<128, true, false>,
                         cudaFuncAttributeMaxDynamicSharedMemorySize, SMEM2);

    lstm_layer<32, false, true><<<128, 256, SMEM1>>>(
        x, w_ih0, w_hh0, b_ih0, b_hh0, h0_ptr, nullptr);
    lstm_layer<128, true, false><<<128, 256, SMEM2>>>(
        h0_ptr, w_ih1, w_hh1, b_ih1, b_hh1, nullptr, last_ptr);
    fc_head<<<B_, 64>>>(last_ptr, fc1_w, fc1_b, fc2_w, fc2_b, out);

    (void)in_sizes; (void)n_in; (void)out_size;
}

// round 8
// speedup vs baseline: 1.0692x; 1.0377x over previous
#include <cuda_runtime.h>
#include <cstdint>

#define B_ 512
#define T_ 256
#define H_ 128
typedef unsigned long long ull;

// scratch: layer-1 hidden sequence (T, B, H) + final h of layer 2
__device__ float g_h0[(size_t)T_ * B_ * H_];
__device__ float g_last[B_ * H_];

// packed fp32x2 FMA: d = a * b + d
#define FMA2(d, a, b) asm("fma.rn.f32x2 %0, %1, %2, %0;" : "+l"(d) : "l"(a), "l"(b))

// store duplicated (v,v) pair: one STS.64, no pack MOVs
__device__ __forceinline__ void st_dup_local(float* p, float v) {
    uint32_t a = (uint32_t)__cvta_generic_to_shared(p);
    asm volatile("st.shared.v2.f32 [%0], {%1, %1};" :: "r"(a), "f"(v) : "memory");
}
__device__ __forceinline__ void st_dup_peer(uint32_t laddr, int peer, float v) {
    uint32_t ra;
    asm volatile("mapa.shared::cluster.u32 %0, %1, %2;" : "=r"(ra) : "r"(laddr), "r"(peer));
    asm volatile("st.shared::cluster.v2.f32 [%0], {%1, %1};" :: "r"(ra), "f"(v) : "memory");
}

__device__ __forceinline__ void cluster_arrive_() {
    asm volatile("barrier.cluster.arrive.aligned;" ::: "memory");
}
__device__ __forceinline__ void cluster_wait_() {
    asm volatile("barrier.cluster.wait.aligned;" ::: "memory");
}

__device__ __forceinline__ float sigmoid_(float x) { return 1.f / (1.f + __expf(-x)); }
__device__ __forceinline__ float tanh_(float x)    { return 2.f / (1.f + __expf(-2.f * x)) - 1.f; }

// Fused LSTM layer. Cluster of 4 CTAs, 16 batch per cluster; CTA rank r owns
// h-dims [r*32, r*32+32) (gate rows g*128 + r*32 + d).
// v rows hold (v,v)-DUPLICATED pairs: 32 floats + 4 pad (stride VS=36).
// 512 threads: K-split-4 across warp quads, 4-col f32x2 accumulators per thread.
// KIN==128 (layer 2): v split into single-buffered input rows + double-buffered h rows.
template <int KIN, bool IN_TB, bool WRITE_SEQ>
__global__ void __cluster_dims__(4, 1, 1) __launch_bounds__(512, 1)
lstm_layer(const float* __restrict__ in,
           const float* __restrict__ w_ih, const float* __restrict__ w_hh,
           const float* __restrict__ b_ih, const float* __restrict__ b_hh,
           float* __restrict__ out_seq, float* __restrict__ out_last)
{
    constexpr int  KTOT  = KIN + H_;
    constexpr int  KQ    = KTOT / 4;         // per-warp-quad K range
    constexpr bool SPLIT = (KIN == H_);      // layer-2 memory layout
    constexpr int  VS    = 36;               // v row stride (floats): 16 dup pairs + pad
    constexpr int  GPAD  = 132;              // g row stride

    extern __shared__ float smem[];
    float* w_s    = smem;                                    // [KTOT][128]
    float* v_in   = w_s + KTOT * 128;                        // SPLIT: [KIN][VS] single
    float* vh0    = SPLIT ? (v_in + KIN * VS) : v_in;        // SPLIT: [128][VS] h buf0
    float* vh1    = vh0 + (SPLIT ? H_ : KTOT) * VS;          //        buf1 (or full v1)
    float* g_s    = vh1 + (SPLIT ? H_ : KTOT) * VS;          // [4][16][GPAD] partials
    float* bias_s = g_s + 4 * 16 * GPAD;                     // [128]
    float* c_s    = bias_s + 128;                            // [16][32]

    const int tid    = threadIdx.x;
    const int rank   = blockIdx.x & 3;
    const int b_base = (blockIdx.x >> 2) * 16;

    // ---- weights into SMEM: w_s[k][col], col = gate*32 + d ----
    for (int idx = tid; idx < 128 * KIN; idx += 512) {
        int col = idx / KIN, k = idx % KIN;
        int grow = (col >> 5) * 128 + rank * 32 + (col & 31);
        w_s[k * 128 + col] = w_ih[grow * KIN + k];
    }
    for (int idx = tid; idx < 128 * H_; idx += 512) {
        int col = idx / H_, k = idx % H_;
        int grow = (col >> 5) * 128 + rank * 32 + (col & 31);
        w_s[(KIN + k) * 128 + col] = w_hh[grow * H_ + k];
    }
    if (tid < 128) {
        int grow = (tid >> 5) * 128 + rank * 32 + (tid & 31);
        bias_s[tid] = b_ih[grow] + b_hh[grow];
    }
    if (tid < 512) c_s[tid] = 0.f;
    // zero h(-1) rows of buffer 0 (first 32 floats of each of the 128 h rows)
    {
        float* hz = SPLIT ? vh0 : (v_in + KIN * VS);
        for (int idx = tid; idx < H_ * 32; idx += 512)
            hz[(idx >> 5) * VS + (idx & 31)] = 0.f;
    }
    // ---- stage t=0 input (dup pairs) ----
    if (IN_TB) {  // (T,B,128): thread -> 4 floats (fixed k, 4 batches)
        int lane = tid & 31, warp = tid >> 5;
        int k  = lane + (warp & 3) * 32;
        int b0 = (warp >> 2) * 4;
        const float* src = in + ((size_t)0 * B_ + b_base + b0) * KIN + k;
        #pragma unroll
        for (int i = 0; i < 4; ++i)
            st_dup_local(v_in + k * VS + 2 * (b0 + i), src[(size_t)i * KIN]);
    } else {      // (B,T,32): thread -> 1 float
        int b = tid >> 5, k = tid & 31;
        float v = in[((size_t)(b_base + b) * T_ + 0) * KIN + k];
        st_dup_local(v_in + k * VS + 2 * b, v);
    }
    __syncthreads();
    cluster_arrive_(); cluster_wait_();

    // ---- thread mapping ----
    const int lane  = tid & 31;
    const int warp  = tid >> 5;
    const int kg    = warp >> 2;                 // K quarter
    const int warpN = warp & 3;
    const int b0    = (lane & 3) * 4;            // 4 batches
    const int c0    = (warpN * 8 + (lane >> 2)) * 4;  // 4 consecutive cols
    const int kbeg  = kg * KQ;
    float* gout = g_s + kg * 16 * GPAD;

    // pointwise mapping: one (b,d) pair per thread
    const int pb = tid >> 5, pd = tid & 31;

    for (int t = 0; t < T_; ++t) {
        float* vhcur = (t & 1) ? vh1 : vh0;
        float* vhnxt = (t & 1) ? vh0 : vh1;

        // ---- prefetch next-step input into registers ----
        float pf[4];
        if (t + 1 < T_) {
            if (IN_TB) {
                int k = lane + (warpN) * 32;
                int bq = (warp >> 2) * 4;
                const float* src = in + ((size_t)(t + 1) * B_ + b_base + bq) * KIN + k;
                #pragma unroll
                for (int i = 0; i < 4; ++i) pf[i] = src[(size_t)i * KIN];
            } else {
                pf[0] = in[((size_t)(b_base + pb) * T_ + (t + 1)) * KIN + pd];
            }
        }

        // ---- GEMM over my K quarter: acc covers (4 batches x 4 cols) ----
        const float* vbase;
        if (SPLIT) vbase = (kg < 2) ? (v_in + kbeg * VS) : (vhcur + (kbeg - KIN) * VS);
        else       vbase = ((t & 1) ? vh1 : vh0) - 0 + kbeg * VS;  // full contiguous buffer
        if (!SPLIT) {
            // contiguous buffers: v_in is buf0 base; vh1 is buf1 base
            vbase = ((t & 1) ? vh1 : v_in) + kbeg * VS;
        }
        const float* wbase = w_s + kbeg * 128 + c0;

        ull acc[4][2];
        #pragma unroll
        for (int bi = 0; bi < 4; ++bi) { acc[bi][0] = 0ull; acc[bi][1] = 0ull; }

        #pragma unroll 8
        for (int kk = 0; kk < KQ; ++kk) {
            const float* vr = vbase + kk * VS;
            ulonglong2 va = *(const ulonglong2*)(vr + b0 * 2);      // dup (b0,b0+1)
            ulonglong2 vb = *(const ulonglong2*)(vr + b0 * 2 + 4);  // dup (b0+2,b0+3)
            ulonglong2 w2 = *(const ulonglong2*)(wbase + kk * 128); // cols c0..c0+3
            FMA2(acc[0][0], va.x, w2.x); FMA2(acc[0][1], va.x, w2.y);
            FMA2(acc[1][0], va.y, w2.x); FMA2(acc[1][1], va.y, w2.y);
            FMA2(acc[2][0], vb.x, w2.x); FMA2(acc[2][1], vb.x, w2.y);
            FMA2(acc[3][0], vb.y, w2.x); FMA2(acc[3][1], vb.y, w2.y);
        }

        // ---- store K-quarter partials ----
        #pragma unroll
        for (int bi = 0; bi < 4; ++bi) {
            *(ull*)(gout + (b0 + bi) * GPAD + c0)     = acc[bi][0];
            *(ull*)(gout + (b0 + bi) * GPAD + c0 + 2) = acc[bi][1];
        }
        __syncthreads();

        // ---- pointwise gates + h broadcast: one (b,d) pair per thread ----
        {
            const float* gb0 = g_s + pb * GPAD + pd;
            float gi = bias_s[pd]      + gb0[0]               + gb0[16*GPAD]
                                       + gb0[32*GPAD]         + gb0[48*GPAD];
            float gf = bias_s[pd + 32] + gb0[32]              + gb0[16*GPAD + 32]
                                       + gb0[32*GPAD + 32]    + gb0[48*GPAD + 32];
            float gg = bias_s[pd + 64] + gb0[64]              + gb0[16*GPAD + 64]
                                       + gb0[32*GPAD + 64]    + gb0[48*GPAD + 64];
            float go = bias_s[pd + 96] + gb0[96]              + gb0[16*GPAD + 96]
                                       + gb0[32*GPAD + 96]    + gb0[48*GPAD + 96];
            float is = sigmoid_(gi);
            float fs = sigmoid_(gf);
            float gt = tanh_(gg);
            float os = sigmoid_(go);
            float c  = fs * c_s[pb * 32 + pd] + is * gt;
            c_s[pb * 32 + pd] = c;
            float h  = os * tanh_(c);

            float* hrow = SPLIT ? (vhnxt + (rank * 32 + pd) * VS)
                                : (((t & 1) ? v_in : vh1) + (KIN + rank * 32 + pd) * VS);
            float* dst = hrow + 2 * pb;
            st_dup_local(dst, h);
            uint32_t la = (uint32_t)__cvta_generic_to_shared(dst);
            if (rank != 0) st_dup_peer(la, 0, h);
            if (rank != 1) st_dup_peer(la, 1, h);
            if (rank != 2) st_dup_peer(la, 2, h);
            if (rank != 3) st_dup_peer(la, 3, h);

            if (WRITE_SEQ) {
                out_seq[((size_t)t * B_ + (b_base + pb)) * H_ + rank * 32 + pd] = h;
            } else if (t == T_ - 1) {
                out_last[(size_t)(b_base + pb) * H_ + rank * 32 + pd] = h;
            }
        }

        // release my h-slice; overlap local input staging with cluster latency
        cluster_arrive_();
        if (t + 1 < T_) {
            if (IN_TB) {
                int k = lane + warpN * 32;
                int bq = (warp >> 2) * 4;
                #pragma unroll
                for (int i = 0; i < 4; ++i)
                    st_dup_local(v_in + k * VS + 2 * (bq + i), pf[i]);
            } else {
                float* vnin = ((t & 1) ? v_in : vh1);  // next step's full buffer
                st_dup_local(vnin + pd * VS + 2 * pb, pf[0]);
            }
        }
        cluster_wait_();
    }
}

// FC head: out[b] = fc2_b + sum_j fc2_w[j] * relu(fc1_b[j] + h1_last[b] . fc1_w[j])
__global__ void __launch_bounds__(64) fc_head(
    const float* __restrict__ last_h,
    const float* __restrict__ fc1_w, const float* __restrict__ fc1_b,
    const float* __restrict__ fc2_w, const float* __restrict__ fc2_b,
    float* __restrict__ out)
{
    int b = blockIdx.x, j = threadIdx.x;
    const float* h = last_h + (size_t)b * H_;
    const float* w = fc1_w + (size_t)j * H_;
    float s = fc1_b[j];
    #pragma unroll 8
    for (int k = 0; k < H_; ++k) s = fmaf(h[k], w[k], s);
    float z = fmaxf(s, 0.f) * fc2_w[j];

    __shared__ float red[2];
    #pragma unroll
    for (int o = 16; o > 0; o >>= 1) z += __shfl_down_sync(0xffffffff, z, o);
    if ((j & 31) == 0) red[j >> 5] = z;
    __syncthreads();
    if (j == 0) out[b] = red[0] + red[1] + fc2_b[0];
}

extern "C" void kernel_launch(void* const* d_in, const int* in_sizes, int n_in,
                              void* d_out, int out_size)
{
    const float* x     = (const float*)d_in[0];
    const float* w_ih0 = (const float*)d_in[1];
    const float* w_hh0 = (const float*)d_in[2];
    const float* b_ih0 = (const float*)d_in[3];
    const float* b_hh0 = (const float*)d_in[4];
    const float* w_ih1 = (const float*)d_in[5];
    const float* w_hh1 = (const float*)d_in[6];
    const float* b_ih1 = (const float*)d_in[7];
    const float* b_hh1 = (const float*)d_in[8];
    const float* fc1_w = (const float*)d_in[9];
    const float* fc1_b = (const float*)d_in[10];
    const float* fc2_w = (const float*)d_in[11];
    const float* fc2_b = (const float*)d_in[12];
    float* out = (float*)d_out;

    float *h0_ptr, *last_ptr;
    cudaGetSymbolAddress((void**)&h0_ptr, g_h0);
    cudaGetSymbolAddress((void**)&last_ptr, g_last);

    // layer1 (no split): w 160*128 + v 2*160*36 + g 4*16*132 + bias 128 + c 512
    constexpr int SMEM1 = (160 * 128 + 2 * 160 * 36 + 4 * 16 * 132 + 128 + 512) * 4; // 164,352
    // layer2 (split):   w 256*128 + v_in 128*36 + vh 2*128*36 + g + bias + c
    constexpr int SMEM2 = (256 * 128 + 3 * 128 * 36 + 4 * 16 * 132 + 128 + 512) * 4; // 222,720

    cudaFuncSetAttribute(lstm_layer<32, false, true>,
                         cudaFuncAttributeMaxDynamicSharedMemorySize, SMEM1);
    cudaFuncSetAttribute(lstm_layer<128, true, false>,
                         cudaFuncAttributeMaxDynamicSharedMemorySize, SMEM2);

    lstm_layer<32, false, true><<<128, 512, SMEM1>>>(
        x, w_ih0, w_hh0, b_ih0, b_hh0, h0_ptr, nullptr);
    lstm_layer<128, true, false><<<128, 512, SMEM2>>>(
        h0_ptr, w_ih1, w_hh1, b_ih1, b_hh1, nullptr, last_ptr);
    fc_head<<<B_, 64>>>(last_ptr, fc1_w, fc1_b, fc2_w, fc2_b, out);

    (void)in_sizes; (void)n_in; (void)out_size;
}

// round 9
// speedup vs baseline: 1.4675x; 1.3725x over previous
#include <cuda_runtime.h>
#include <cstdint>

#define B_ 512
#define T_ 256
#define H_ 128
typedef unsigned long long ull;

// scratch: layer-1 hidden sequence (T, B, H) + final h of layer 2
__device__ float g_h0[(size_t)T_ * B_ * H_];
__device__ float g_last[B_ * H_];

// packed fp32x2 FMA: d = a * b + d
#define FMA2(d, a, b) asm("fma.rn.f32x2 %0, %1, %2, %0;" : "+l"(d) : "l"(a), "l"(b))
// duplicate a float into both halves of a 64-bit reg
#define DUP2(d, f)    asm("mov.b64 %0, {%1, %1};" : "=l"(d) : "f"(f))

__device__ __forceinline__ void st_peer_f32(uint32_t laddr, int peer, float v) {
    uint32_t ra;
    asm volatile("mapa.shared::cluster.u32 %0, %1, %2;" : "=r"(ra) : "r"(laddr), "r"(peer));
    asm volatile("st.shared::cluster.f32 [%0], %1;" :: "r"(ra), "f"(v) : "memory");
}
__device__ __forceinline__ void cluster_arrive_() {
    asm volatile("barrier.cluster.arrive.aligned;" ::: "memory");
}
__device__ __forceinline__ void cluster_wait_() {
    asm volatile("barrier.cluster.wait.aligned;" ::: "memory");
}

__device__ __forceinline__ float sigmoid_(float x) { return 1.f / (1.f + __expf(-x)); }
__device__ __forceinline__ float tanh_(float x)    { return 2.f / (1.f + __expf(-2.f * x)) - 1.f; }

// Fused LSTM layer. Cluster of 4 CTAs, 16 batch per cluster; CTA rank r owns
// h-dims [r*32, r*32+32) (gate rows g*128 + r*32 + d).
// 256 threads, 8 warps: K-split-4 (warp pairs), per-thread tile = 8 batches x
// (4 gates of one d). v rows PLAIN 16 floats (stride VS=20). Batch-packed f32x2
// accumulators; w duplicated per-k via MOV (static operand).
template <int KIN, bool IN_TB, bool WRITE_SEQ>
__global__ void __cluster_dims__(4, 1, 1) __launch_bounds__(256, 1)
lstm_layer(const float* __restrict__ in,
           const float* __restrict__ w_ih, const float* __restrict__ w_hh,
           const float* __restrict__ b_ih, const float* __restrict__ b_hh,
           float* __restrict__ out_seq, float* __restrict__ out_last)
{
    constexpr int  KTOT  = KIN + H_;
    constexpr int  KQ    = KTOT / 4;
    constexpr bool SPLIT = (KIN == H_);      // layer-2 memory layout
    constexpr int  VS    = 20;               // v row stride: 16 floats + pad

    extern __shared__ float smem[];
    float* w_s    = smem;                                  // [KTOT][128]
    float* v_in   = w_s + KTOT * 128;                      // SPLIT: [KIN][VS] single
    float* vh0    = SPLIT ? (v_in + KIN * VS) : v_in;      // SPLIT: [128][VS] h buf0
    float* vh1    = vh0 + (SPLIT ? H_ : KTOT) * VS;        // buf1 (or full buffer 1)
    float* g_s    = vh1 + (SPLIT ? H_ : KTOT) * VS;        // [4s][2bg][4bp][4g][64]
    float* bias_s = g_s + 8192;                            // [128]
    float* c_s    = bias_s + 128;                          // [16][32]

    const int tid    = threadIdx.x;
    const int rank   = blockIdx.x & 3;
    const int b_base = (blockIdx.x >> 2) * 16;

    // ---- weights into SMEM: w_s[k][col], col = gate*32 + d ----
    for (int idx = tid; idx < 128 * KIN; idx += 256) {
        int col = idx / KIN, k = idx % KIN;
        int grow = (col >> 5) * 128 + rank * 32 + (col & 31);
        w_s[k * 128 + col] = w_ih[grow * KIN + k];
    }
    for (int idx = tid; idx < 128 * H_; idx += 256) {
        int col = idx / H_, k = idx % H_;
        int grow = (col >> 5) * 128 + rank * 32 + (col & 31);
        w_s[(KIN + k) * 128 + col] = w_hh[grow * H_ + k];
    }
    if (tid < 128) {
        int grow = (tid >> 5) * 128 + rank * 32 + (tid & 31);
        bias_s[tid] = b_ih[grow] + b_hh[grow];
    }
    for (int idx = tid; idx < 512; idx += 256) c_s[idx] = 0.f;
    {   // zero h(-1) rows of buffer 0
        float* hz = SPLIT ? vh0 : (v_in + KIN * VS);
        for (int idx = tid; idx < H_ * 16; idx += 256)
            hz[(idx >> 4) * VS + (idx & 15)] = 0.f;
    }
    // ---- stage t=0 input ----
    if (IN_TB) {  // (T,B,128): thread -> 8 consecutive k of one batch
        int b = tid >> 4, k0 = (tid & 15) * 8;
        const float* src = in + ((size_t)0 * B_ + b_base + b) * KIN + k0;
        float4 a = *(const float4*)src;
        float4 c4 = *(const float4*)(src + 4);
        v_in[(k0 + 0) * VS + b] = a.x;  v_in[(k0 + 1) * VS + b] = a.y;
        v_in[(k0 + 2) * VS + b] = a.z;  v_in[(k0 + 3) * VS + b] = a.w;
        v_in[(k0 + 4) * VS + b] = c4.x; v_in[(k0 + 5) * VS + b] = c4.y;
        v_in[(k0 + 6) * VS + b] = c4.z; v_in[(k0 + 7) * VS + b] = c4.w;
    } else {      // (B,T,32): 2 floats per thread
        #pragma unroll
        for (int j = 0; j < 2; ++j) {
            int idx = tid + j * 256;
            int b = idx >> 5, k = idx & 31;
            v_in[k * VS + b] = in[((size_t)(b_base + b) * T_ + 0) * KIN + k];
        }
    }
    __syncthreads();
    cluster_arrive_(); cluster_wait_();

    // ---- GEMM thread mapping ----
    const int lane = tid & 31;
    const int warp = tid >> 5;
    const int kg   = warp >> 1;          // K quarter
    const int bg   = warp & 1;           // batch half (8 batches)
    const int b0   = bg * 8;
    const int kbeg = kg * KQ;
    float* gslice = g_s + ((kg * 2 + bg) * 16) * 64;   // + (bp*4+gate)*64

    // pointwise mapping: 2 (b,d) pairs per thread, p = tid + j*256
    const int pb0 = tid >> 5, pd = tid & 31;

    for (int t = 0; t < T_; ++t) {
        // ---- prefetch next-step input into registers ----
        float  pf0 = 0.f, pf1 = 0.f;
        float4 pfa, pfb;
        if (t + 1 < T_) {
            if (IN_TB) {
                int b = tid >> 4, k0 = (tid & 15) * 8;
                const float* src = in + ((size_t)(t + 1) * B_ + b_base + b) * KIN + k0;
                pfa = *(const float4*)src;
                pfb = *(const float4*)(src + 4);
            } else {
                int i0 = tid, i1 = tid + 256;
                pf0 = in[((size_t)(b_base + (i0 >> 5)) * T_ + (t + 1)) * KIN + (i0 & 31)];
                pf1 = in[((size_t)(b_base + (i1 >> 5)) * T_ + (t + 1)) * KIN + (i1 & 31)];
            }
        }

        // ---- GEMM over my K quarter: acc[gate][bp] (4 gates of d=lane, 8 batches) ----
        const float* vbase;
        if (SPLIT) vbase = (kg < 2) ? (v_in + kbeg * VS)
                                    : (((t & 1) ? vh1 : vh0) + (kbeg - KIN) * VS);
        else       vbase = (((t & 1) ? vh1 : v_in)) + kbeg * VS;
        const float* wbase = w_s + kbeg * 128 + lane;

        ull acc[4][4];
        #pragma unroll
        for (int g = 0; g < 4; ++g)
            #pragma unroll
            for (int bp = 0; bp < 4; ++bp) acc[g][bp] = 0ull;

        #pragma unroll 8
        for (int kk = 0; kk < KQ; ++kk) {
            const float* vr = vbase + kk * VS + b0;
            ulonglong2 va = *(const ulonglong2*)vr;        // (b0,b1),(b2,b3)
            ulonglong2 vb = *(const ulonglong2*)(vr + 4);  // (b4,b5),(b6,b7)
            const float* wr = wbase + kk * 128;
            float w0 = wr[0], w1 = wr[32], w2 = wr[64], w3 = wr[96];
            ull d0, d1, d2, d3;
            DUP2(d0, w0); DUP2(d1, w1); DUP2(d2, w2); DUP2(d3, w3);
            FMA2(acc[0][0], va.x, d0); FMA2(acc[0][1], va.y, d0);
            FMA2(acc[0][2], vb.x, d0); FMA2(acc[0][3], vb.y, d0);
            FMA2(acc[1][0], va.x, d1); FMA2(acc[1][1], va.y, d1);
            FMA2(acc[1][2], vb.x, d1); FMA2(acc[1][3], vb.y, d1);
            FMA2(acc[2][0], va.x, d2); FMA2(acc[2][1], va.y, d2);
            FMA2(acc[2][2], vb.x, d2); FMA2(acc[2][3], vb.y, d2);
            FMA2(acc[3][0], va.x, d3); FMA2(acc[3][1], va.y, d3);
            FMA2(acc[3][2], vb.x, d3); FMA2(acc[3][3], vb.y, d3);
        }

        // ---- store K-quarter partials: STS.64, lane-contiguous (no conflicts) ----
        #pragma unroll
        for (int bp = 0; bp < 4; ++bp)
            #pragma unroll
            for (int g = 0; g < 4; ++g)
                *(ull*)(gslice + (bp * 4 + g) * 64 + lane * 2) = acc[g][bp];
        __syncthreads();

        // ---- pointwise gates + h broadcast: 2 (b,d) pairs per thread ----
        #pragma unroll
        for (int j = 0; j < 2; ++j) {
            int b   = pb0 + j * 8;
            int bg2 = b >> 3, bp2 = (b >> 1) & 3, par = b & 1;
            float gv[4];
            #pragma unroll
            for (int g = 0; g < 4; ++g) {
                float s = bias_s[g * 32 + pd];
                #pragma unroll
                for (int sl = 0; sl < 4; ++sl)
                    s += g_s[((sl * 2 + bg2) * 16 + bp2 * 4 + g) * 64 + pd * 2 + par];
                gv[g] = s;
            }
            float is = sigmoid_(gv[0]);
            float fs = sigmoid_(gv[1]);
            float gt = tanh_(gv[2]);
            float os = sigmoid_(gv[3]);
            float c  = fs * c_s[b * 32 + pd] + is * gt;
            c_s[b * 32 + pd] = c;
            float h  = os * tanh_(c);

            float* hrow = SPLIT ? (((t & 1) ? vh0 : vh1) + (rank * 32 + pd) * VS)
                                : (((t & 1) ? v_in : vh1) + (KIN + rank * 32 + pd) * VS);
            float* dst = hrow + b;
            *dst = h;
            uint32_t la = (uint32_t)__cvta_generic_to_shared(dst);
            if (rank != 0) st_peer_f32(la, 0, h);
            if (rank != 1) st_peer_f32(la, 1, h);
            if (rank != 2) st_peer_f32(la, 2, h);
            if (rank != 3) st_peer_f32(la, 3, h);

            if (WRITE_SEQ) {
                out_seq[((size_t)t * B_ + (b_base + b)) * H_ + rank * 32 + pd] = h;
            } else if (t == T_ - 1) {
                out_last[(size_t)(b_base + b) * H_ + rank * 32 + pd] = h;
            }
        }

        // release my h-slice; overlap local input staging with cluster latency
        cluster_arrive_();
        if (t + 1 < T_) {
            if (IN_TB) {
                int b = tid >> 4, k0 = (tid & 15) * 8;
                v_in[(k0 + 0) * VS + b] = pfa.x; v_in[(k0 + 1) * VS + b] = pfa.y;
                v_in[(k0 + 2) * VS + b] = pfa.z; v_in[(k0 + 3) * VS + b] = pfa.w;
                v_in[(k0 + 4) * VS + b] = pfb.x; v_in[(k0 + 5) * VS + b] = pfb.y;
                v_in[(k0 + 6) * VS + b] = pfb.z; v_in[(k0 + 7) * VS + b] = pfb.w;
            } else {
                float* vn = (t & 1) ? v_in : vh1;   // next step's buffer
                int i0 = tid, i1 = tid + 256;
                vn[(i0 & 31) * VS + (i0 >> 5)] = pf0;
                vn[(i1 & 31) * VS + (i1 >> 5)] = pf1;
            }
        }
        cluster_wait_();
    }
}

// FC head: out[b] = fc2_b + sum_j fc2_w[j] * relu(fc1_b[j] + h1_last[b] . fc1_w[j])
__global__ void __launch_bounds__(64) fc_head(
    const float* __restrict__ last_h,
    const float* __restrict__ fc1_w, const float* __restrict__ fc1_b,
    const float* __restrict__ fc2_w, const float* __restrict__ fc2_b,
    float* __restrict__ out)
{
    int b = blockIdx.x, j = threadIdx.x;
    const float* h = last_h + (size_t)b * H_;
    const float* w = fc1_w + (size_t)j * H_;
    float s = fc1_b[j];
    #pragma unroll 8
    for (int k = 0; k < H_; ++k) s = fmaf(h[k], w[k], s);
    float z = fmaxf(s, 0.f) * fc2_w[j];

    __shared__ float red[2];
    #pragma unroll
    for (int o = 16; o > 0; o >>= 1) z += __shfl_down_sync(0xffffffff, z, o);
    if ((j & 31) == 0) red[j >> 5] = z;
    __syncthreads();
    if (j == 0) out[b] = red[0] + red[1] + fc2_b[0];
}

extern "C" void kernel_launch(void* const* d_in, const int* in_sizes, int n_in,
                              void* d_out, int out_size)
{
    const float* x     = (const float*)d_in[0];
    const float* w_ih0 = (const float*)d_in[1];
    const float* w_hh0 = (const float*)d_in[2];
    const float* b_ih0 = (const float*)d_in[3];
    const float* b_hh0 = (const float*)d_in[4];
    const float* w_ih1 = (const float*)d_in[5];
    const float* w_hh1 = (const float*)d_in[6];
    const float* b_ih1 = (const float*)d_in[7];
    const float* b_hh1 = (const float*)d_in[8];
    const float* fc1_w = (const float*)d_in[9];
    const float* fc1_b = (const float*)d_in[10];
    const float* fc2_w = (const float*)d_in[11];
    const float* fc2_b = (const float*)d_in[12];
    float* out = (float*)d_out;

    float *h0_ptr, *last_ptr;
    cudaGetSymbolAddress((void**)&h0_ptr, g_h0);
    cudaGetSymbolAddress((void**)&last_ptr, g_last);

    // layer1: w 160*128 + v 2*160*20 + g 8192 + bias 128 + c 512
    constexpr int SMEM1 = (160 * 128 + 2 * 160 * 20 + 8192 + 128 + 512) * 4;  // 142,848
    // layer2: w 256*128 + v 3*128*20 + g 8192 + bias 128 + c 512
    constexpr int SMEM2 = (256 * 128 + 3 * 128 * 20 + 8192 + 128 + 512) * 4;  // 197,120

    cudaFuncSetAttribute(lstm_layer<32, false, true>,
                         cudaFuncAttributeMaxDynamicSharedMemorySize, SMEM1);
    cudaFuncSetAttribute(lstm_layer<128, true, false>,
                         cudaFuncAttributeMaxDynamicSharedMemorySize, SMEM2);

    lstm_layer<32, false, true><<<128, 256, SMEM1>>>(
        x, w_ih0, w_hh0, b_ih0, b_hh0, h0_ptr, nullptr);
    lstm_layer<128, true, false><<<128, 256, SMEM2>>>(
        h0_ptr, w_ih1, w_hh1, b_ih1, b_hh1, nullptr, last_ptr);
    fc_head<<<B_, 64>>>(last_ptr, fc1_w, fc1_b, fc2_w, fc2_b, out);

    (void)in_sizes; (void)n_in; (void)out_size;
}